// round 10
// baseline (speedup 1.0000x reference)
#include <cuda_runtime.h>

// B=8192, T=2048, H=51
#define B_   8192
#define T_   2048
#define H_   51
#define CP   224            // 56*4 gate-interleaved cols (u=51..55 zero pad)
#define NTH  448
#define GRPT 224
#define RS1  140            // H1D row stride (floats) - conflict-free writes
#define H1BUF (56*RS1)      // 7840

typedef unsigned long long u64;

__device__ __forceinline__ u64 pack2(float lo, float hi) {
    u64 d; asm("mov.b64 %0, {%1, %2};" : "=l"(d) : "f"(lo), "f"(hi)); return d;
}
__device__ __forceinline__ void unpack2(u64 v, float& lo, float& hi) {
    asm("mov.b64 {%0, %1}, %2;" : "=f"(lo), "=f"(hi) : "l"(v));
}
__device__ __forceinline__ u64 fma2(u64 a, u64 b, u64 c) {
    u64 d; asm("fma.rn.f32x2 %0, %1, %2, %3;" : "=l"(d) : "l"(a), "l"(b), "l"(c)); return d;
}
__device__ __forceinline__ float ex2f(float x) { float r; asm("ex2.approx.f32 %0, %1;" : "=f"(r) : "f"(x)); return r; }
__device__ __forceinline__ float rcpf(float x) { float r; asm("rcp.approx.f32 %0, %1;" : "=f"(r) : "f"(x)); return r; }
__device__ __forceinline__ float sigm(float x) {
    return rcpf(1.0f + ex2f(-1.4426950408889634f * x));
}
__device__ __forceinline__ float tanh_(float x) {
    float e = ex2f(2.8853900817779268f * x);
    return 1.0f - 2.0f * rcpf(e + 1.0f);
}

// Smem layout (float offsets)
#define OFF_W1   0           // [51][224]
#define OFF_W2A  11424
#define OFF_W2B  22848
#define OFF_H1D  34272       // [2][56][140] duplicated (h,h)
#define OFF_H2   49952       // [56][64] plain
#define OFF_B1   53536       // 224
#define OFF_WI1  53760
#define OFF_B2   53984
#define OFF_WL   54208       // 60 (WL[56]=b_lin, pads zero)
#define OFF_YP   54268       // [2][28][64]
#define OFF_XS   57852       // [2][64]
#define SMEM_FLOATS 57980    // 231,920 B

__global__ __launch_bounds__(NTH, 1)
void lstm_rnn_kernel(const float* __restrict__ x,
                     const float* __restrict__ Wih1, const float* __restrict__ Whh1,
                     const float* __restrict__ bih1, const float* __restrict__ bhh1,
                     const float* __restrict__ Wih2, const float* __restrict__ Whh2,
                     const float* __restrict__ bih2, const float* __restrict__ bhh2,
                     const float* __restrict__ Wlin, const float* __restrict__ blin,
                     float* __restrict__ out)
{
    extern __shared__ float sm[];
    float* W1s  = sm + OFF_W1;
    float* W2as = sm + OFF_W2A;
    float* W2bs = sm + OFF_W2B;
    float* H1D  = sm + OFF_H1D;
    float* H2   = sm + OFF_H2;
    float* B1s  = sm + OFF_B1;
    float* WI1s = sm + OFF_WI1;
    float* B2s  = sm + OFF_B2;
    float* WLs  = sm + OFF_WL;
    float* YP   = sm + OFF_YP;
    float* XS   = sm + OFF_XS;

    const int tid = threadIdx.x;

    // ---- stage weights gate-interleaved, k-major: W[k][u*4+g] = Wxx[g*51+u][k]
    for (int idx = tid; idx < H_ * CP; idx += NTH) {
        int kk = idx / CP, c = idx - kk * CP;
        int u = c >> 2, g = c & 3;
        float w1 = 0.f, wa = 0.f, wb = 0.f;
        if (u < H_) {
            int j = g * H_ + u;
            w1 = Whh1[j * H_ + kk];
            wa = Wih2[j * H_ + kk];
            wb = Whh2[j * H_ + kk];
        }
        W1s[idx] = w1; W2as[idx] = wa; W2bs[idx] = wb;
    }
    for (int c = tid; c < CP; c += NTH) {
        int u = c >> 2, g = c & 3;
        bool v = (u < H_);
        int j = g * H_ + u;
        B1s[c]  = v ? (bih1[j] + bhh1[j]) : 0.f;
        WI1s[c] = v ? Wih1[j] : 0.f;
        B2s[c]  = v ? (bih2[j] + bhh2[j]) : 0.f;
    }
    if (tid < 60) WLs[tid] = (tid < H_) ? Wlin[tid] : ((tid == 56) ? blin[0] : 0.f);
    for (int idx = tid; idx < 2 * H1BUF; idx += NTH) H1D[idx] = 0.f;
    for (int idx = tid; idx < 56 * 64; idx += NTH)   H2[idx]  = 0.f;
    for (int idx = tid; idx < 3584; idx += NTH)      YP[idx]  = 0.f;
    __syncthreads();

    // roles: threads 0-223 (grp0) = layer1 + y/x service; 224-447 (grp1) = layer2
    const int grp = (tid >= GRPT);
    const int lt  = grp ? tid - GRPT : tid;
    const int ug  = lt >> 3;        // 0..27: cols [ug*8, ug*8+8) = u {2ug, 2ug+1}
    const int mg  = lt & 7;         // 8 m-rows per thread
    const int cb  = ug * 8;
    const int mb  = mg * 8;
    const int ub  = ug * 2;
    const int m0  = blockIdx.x * 64;

    u64 acc[32];                    // 8 m x 4 u64 (8 gate cols)
    float cr[16];                   // c-state: 8 m x 2 u
#pragma unroll
    for (int q = 0; q < 16; ++q) cr[q] = 0.f;

    // ---- prologue (grp0): gates1(0) = b1 + x(0)*Wih1  (h1(-1)=0) ----
    if (!grp) {
        ulonglong2 b01 = *(const ulonglong2*)(B1s + cb);
        ulonglong2 b23 = *(const ulonglong2*)(B1s + cb + 4);
        ulonglong2 w01 = *(const ulonglong2*)(WI1s + cb);
        ulonglong2 w23 = *(const ulonglong2*)(WI1s + cb + 4);
#pragma unroll
        for (int mm = 0; mm < 8; ++mm) {
            float xv = x[(size_t)(m0 + mb + mm) * T_];
            u64 xd = pack2(xv, xv);
            acc[mm*4+0] = fma2(xd, w01.x, b01.x);
            acc[mm*4+1] = fma2(xd, w01.y, b01.y);
            acc[mm*4+2] = fma2(xd, w23.x, b23.x);
            acc[mm*4+3] = fma2(xd, w23.y, b23.y);
        }
    }

    for (int i = 0; i <= T_; ++i) {
        // ================= Segment A =================
        if (!grp) {
            if (lt < 64) {
                // stage x for step i+1
                int tn = (i + 1 < T_) ? (i + 1) : (T_ - 1);
                XS[((i + 1) & 1) * 64 + lt] = x[(size_t)(m0 + lt) * T_ + tn];
                // y writer: step i-2
                if (i >= 2) {
                    const float* yp = YP + (i & 1) * 1792;
                    float y = WLs[56];
#pragma unroll
                    for (int j = 0; j < 28; ++j) y += yp[j * 64 + lt];
                    out[(size_t)(m0 + lt) * T_ + (i - 2)] = y;
                }
            }
            // activation layer1, step i -> h1(i)  (dup, buffer i&1)
            if (i < T_) {
                float* Hw = H1D + (i & 1) * H1BUF;
#pragma unroll
                for (int mm = 0; mm < 8; ++mm) {
                    float i0,f0,g0,o0,i1,f1,g1,o1;
                    unpack2(acc[mm*4+0], i0, f0);
                    unpack2(acc[mm*4+1], g0, o0);
                    unpack2(acc[mm*4+2], i1, f1);
                    unpack2(acc[mm*4+3], g1, o1);
                    float c0 = sigm(f0) * cr[mm*2+0] + sigm(i0) * tanh_(g0);
                    float c1 = sigm(f1) * cr[mm*2+1] + sigm(i1) * tanh_(g1);
                    cr[mm*2+0] = c0; cr[mm*2+1] = c1;
                    float h0 = sigm(o0) * tanh_(c0);
                    float h1v = sigm(o1) * tanh_(c1);
                    *(float2*)(Hw + (ub + 0) * RS1 + (mb + mm) * 2) = make_float2(h0, h0);
                    *(float2*)(Hw + (ub + 1) * RS1 + (mb + mm) * 2) = make_float2(h1v, h1v);
                }
            }
        } else {
            // GEMM layer2, step i-1: Wih2*h1(i-1) + Whh2*h2(i-2) + b2
            if (i >= 1) {
                ulonglong2 b01 = *(const ulonglong2*)(B2s + cb);
                ulonglong2 b23 = *(const ulonglong2*)(B2s + cb + 4);
#pragma unroll
                for (int mm = 0; mm < 8; ++mm) {
                    acc[mm*4+0] = b01.x; acc[mm*4+1] = b01.y;
                    acc[mm*4+2] = b23.x; acc[mm*4+3] = b23.y;
                }
                const float* H1r = H1D + ((i - 1) & 1) * H1BUF;
#pragma unroll 1
                for (int kk = 0; kk < H_; ++kk) {
                    const float* hp = H1r + kk * RS1 + mb * 2;
                    ulonglong2 ha = *(const ulonglong2*)(hp);
                    ulonglong2 hb = *(const ulonglong2*)(hp + 4);
                    ulonglong2 hc = *(const ulonglong2*)(hp + 8);
                    ulonglong2 hd = *(const ulonglong2*)(hp + 12);
                    float4 p0 = *(const float4*)(H2 + kk * 64 + mb);
                    float4 p1 = *(const float4*)(H2 + kk * 64 + mb + 4);
                    u64 h2v[8];
                    h2v[0] = pack2(p0.x, p0.x); h2v[1] = pack2(p0.y, p0.y);
                    h2v[2] = pack2(p0.z, p0.z); h2v[3] = pack2(p0.w, p0.w);
                    h2v[4] = pack2(p1.x, p1.x); h2v[5] = pack2(p1.y, p1.y);
                    h2v[6] = pack2(p1.z, p1.z); h2v[7] = pack2(p1.w, p1.w);
                    const float* wA = W2as + kk * CP + cb;
                    const float* wB = W2bs + kk * CP + cb;
                    ulonglong2 wa01 = *(const ulonglong2*)(wA);
                    ulonglong2 wa23 = *(const ulonglong2*)(wA + 4);
                    ulonglong2 wb01 = *(const ulonglong2*)(wB);
                    ulonglong2 wb23 = *(const ulonglong2*)(wB + 4);
                    u64 h1v[8] = {ha.x, ha.y, hb.x, hb.y, hc.x, hc.y, hd.x, hd.y};
#pragma unroll
                    for (int mm = 0; mm < 8; ++mm) {
                        acc[mm*4+0] = fma2(h1v[mm], wa01.x, acc[mm*4+0]);
                        acc[mm*4+1] = fma2(h1v[mm], wa01.y, acc[mm*4+1]);
                        acc[mm*4+2] = fma2(h1v[mm], wa23.x, acc[mm*4+2]);
                        acc[mm*4+3] = fma2(h1v[mm], wa23.y, acc[mm*4+3]);
                        acc[mm*4+0] = fma2(h2v[mm], wb01.x, acc[mm*4+0]);
                        acc[mm*4+1] = fma2(h2v[mm], wb01.y, acc[mm*4+1]);
                        acc[mm*4+2] = fma2(h2v[mm], wb23.x, acc[mm*4+2]);
                        acc[mm*4+3] = fma2(h2v[mm], wb23.y, acc[mm*4+3]);
                    }
                }
            }
        }
        __syncthreads();

        // ================= Segment B =================
        if (!grp) {
            // GEMM layer1, step i+1: Whh1*h1(i) + x(i+1)*Wih1 + b1
            if (i + 1 < T_) {
                ulonglong2 b01 = *(const ulonglong2*)(B1s + cb);
                ulonglong2 b23 = *(const ulonglong2*)(B1s + cb + 4);
#pragma unroll
                for (int mm = 0; mm < 8; ++mm) {
                    acc[mm*4+0] = b01.x; acc[mm*4+1] = b01.y;
                    acc[mm*4+2] = b23.x; acc[mm*4+3] = b23.y;
                }
                const float* Hr = H1D + (i & 1) * H1BUF;
#pragma unroll 1
                for (int kk = 0; kk < H_; ++kk) {
                    const float* hp = Hr + kk * RS1 + mb * 2;
                    ulonglong2 ha = *(const ulonglong2*)(hp);
                    ulonglong2 hb = *(const ulonglong2*)(hp + 4);
                    ulonglong2 hc = *(const ulonglong2*)(hp + 8);
                    ulonglong2 hd = *(const ulonglong2*)(hp + 12);
                    const float* wP = W1s + kk * CP + cb;
                    ulonglong2 w01 = *(const ulonglong2*)(wP);
                    ulonglong2 w23 = *(const ulonglong2*)(wP + 4);
                    u64 h1v[8] = {ha.x, ha.y, hb.x, hb.y, hc.x, hc.y, hd.x, hd.y};
#pragma unroll
                    for (int mm = 0; mm < 8; ++mm) {
                        acc[mm*4+0] = fma2(h1v[mm], w01.x, acc[mm*4+0]);
                        acc[mm*4+1] = fma2(h1v[mm], w01.y, acc[mm*4+1]);
                        acc[mm*4+2] = fma2(h1v[mm], w23.x, acc[mm*4+2]);
                        acc[mm*4+3] = fma2(h1v[mm], w23.y, acc[mm*4+3]);
                    }
                }
                // x-term (from smem stage)
                float4 xa = *(const float4*)(XS + ((i + 1) & 1) * 64 + mb);
                float4 xb = *(const float4*)(XS + ((i + 1) & 1) * 64 + mb + 4);
                ulonglong2 w01 = *(const ulonglong2*)(WI1s + cb);
                ulonglong2 w23 = *(const ulonglong2*)(WI1s + cb + 4);
                float xsv[8] = {xa.x, xa.y, xa.z, xa.w, xb.x, xb.y, xb.z, xb.w};
#pragma unroll
                for (int mm = 0; mm < 8; ++mm) {
                    u64 xd = pack2(xsv[mm], xsv[mm]);
                    acc[mm*4+0] = fma2(xd, w01.x, acc[mm*4+0]);
                    acc[mm*4+1] = fma2(xd, w01.y, acc[mm*4+1]);
                    acc[mm*4+2] = fma2(xd, w23.x, acc[mm*4+2]);
                    acc[mm*4+3] = fma2(xd, w23.y, acc[mm*4+3]);
                }
            }
        } else {
            // activation layer2, step i-1 -> h2(i-1), y partials
            if (i >= 1) {
                float h0a[8], h1a[8];
#pragma unroll
                for (int mm = 0; mm < 8; ++mm) {
                    float i0,f0,g0,o0,i1,f1,g1,o1;
                    unpack2(acc[mm*4+0], i0, f0);
                    unpack2(acc[mm*4+1], g0, o0);
                    unpack2(acc[mm*4+2], i1, f1);
                    unpack2(acc[mm*4+3], g1, o1);
                    float c0 = sigm(f0) * cr[mm*2+0] + sigm(i0) * tanh_(g0);
                    float c1 = sigm(f1) * cr[mm*2+1] + sigm(i1) * tanh_(g1);
                    cr[mm*2+0] = c0; cr[mm*2+1] = c1;
                    h0a[mm] = sigm(o0) * tanh_(c0);
                    h1a[mm] = sigm(o1) * tanh_(c1);
                }
                *(float4*)(H2 + (ub + 0) * 64 + mb)     = make_float4(h0a[0], h0a[1], h0a[2], h0a[3]);
                *(float4*)(H2 + (ub + 0) * 64 + mb + 4) = make_float4(h0a[4], h0a[5], h0a[6], h0a[7]);
                *(float4*)(H2 + (ub + 1) * 64 + mb)     = make_float4(h1a[0], h1a[1], h1a[2], h1a[3]);
                *(float4*)(H2 + (ub + 1) * 64 + mb + 4) = make_float4(h1a[4], h1a[5], h1a[6], h1a[7]);
                float wl0 = WLs[ub], wl1 = WLs[ub + 1];
                float py[8];
#pragma unroll
                for (int mm = 0; mm < 8; ++mm)
                    py[mm] = wl0 * h0a[mm] + wl1 * h1a[mm];
                float* ypw = YP + ((i - 1) & 1) * 1792 + ug * 64 + mb;
                *(float4*)(ypw)     = make_float4(py[0], py[1], py[2], py[3]);
                *(float4*)(ypw + 4) = make_float4(py[4], py[5], py[6], py[7]);
            }
        }
        __syncthreads();
    }

    // final y for step T-1
    if (tid < 64) {
        const float* yp = YP + ((T_ - 1) & 1) * 1792;
        float y = WLs[56];
#pragma unroll
        for (int j = 0; j < 28; ++j) y += yp[j * 64 + tid];
        out[(size_t)(m0 + tid) * T_ + (T_ - 1)] = y;
    }
}

extern "C" void kernel_launch(void* const* d_in, const int* in_sizes, int n_in,
                              void* d_out, int out_size) {
    const float* x    = (const float*)d_in[0];
    const float* Wih1 = (const float*)d_in[1];
    const float* Whh1 = (const float*)d_in[2];
    const float* bih1 = (const float*)d_in[3];
    const float* bhh1 = (const float*)d_in[4];
    const float* Wih2 = (const float*)d_in[5];
    const float* Whh2 = (const float*)d_in[6];
    const float* bih2 = (const float*)d_in[7];
    const float* bhh2 = (const float*)d_in[8];
    const float* Wlin = (const float*)d_in[9];
    const float* blin = (const float*)d_in[10];
    float* out = (float*)d_out;

    size_t smem = SMEM_FLOATS * sizeof(float);   // ~226.5 KB
    cudaFuncSetAttribute(lstm_rnn_kernel,
                         cudaFuncAttributeMaxDynamicSharedMemorySize, (int)smem);
    lstm_rnn_kernel<<<B_ / 64, NTH, smem>>>(x, Wih1, Whh1, bih1, bhh1,
                                            Wih2, Whh2, bih2, bhh2,
                                            Wlin, blin, out);
}

// round 12
// speedup vs baseline: 1.6600x; 1.6600x over previous
#include <cuda_runtime.h>

// B=8192, T=2048, H=51
#define B_   8192
#define T_   2048
#define H_   51
#define CP   224            // 56*4 gate-interleaved cols (u=51..55 zero pad)
#define NTH  256
#define RS   128            // H row stride (floats), duplicated (h,h) layout
#define H1BUF (56*RS)       // 7168

typedef unsigned long long u64;

__device__ __forceinline__ u64 pack2(float lo, float hi) {
    u64 d; asm("mov.b64 %0, {%1, %2};" : "=l"(d) : "f"(lo), "f"(hi)); return d;
}
__device__ __forceinline__ void unpack2(u64 v, float& lo, float& hi) {
    asm("mov.b64 {%0, %1}, %2;" : "=f"(lo), "=f"(hi) : "l"(v));
}
__device__ __forceinline__ u64 fma2(u64 a, u64 b, u64 c) {
    u64 d; asm("fma.rn.f32x2 %0, %1, %2, %3;" : "=l"(d) : "l"(a), "l"(b), "l"(c)); return d;
}
__device__ __forceinline__ float ex2f(float x) { float r; asm("ex2.approx.f32 %0, %1;" : "=f"(r) : "f"(x)); return r; }
__device__ __forceinline__ float rcpf(float x) { float r; asm("rcp.approx.f32 %0, %1;" : "=f"(r) : "f"(x)); return r; }
__device__ __forceinline__ float sigm(float x) {
    return rcpf(1.0f + ex2f(-1.4426950408889634f * x));
}
__device__ __forceinline__ float tanh_(float x) {
    float e = ex2f(2.8853900817779268f * x);
    return 1.0f - 2.0f * rcpf(e + 1.0f);
}

// Smem layout (float offsets)
#define OFF_W1   0           // [51][224]
#define OFF_W2A  11424
#define OFF_W2B  22848
#define OFF_H1D  34272       // [2][56][128] duplicated (h,h)
#define OFF_H2D  48608       // [56][128]    duplicated (h,h), single buffer
#define OFF_B1   55776       // 224
#define OFF_WI1  56000
#define OFF_B2   56224
#define OFF_WL   56448       // 64  (WL[56]=b_lin)
#define OFF_YP   56512       // [2][8][64]
#define OFF_XS   57536       // [2][64]
#define SMEM_FLOATS 57664    // 230,656 B

__global__ __launch_bounds__(NTH, 1)
void lstm_rnn_kernel(const float* __restrict__ x,
                     const float* __restrict__ Wih1, const float* __restrict__ Whh1,
                     const float* __restrict__ bih1, const float* __restrict__ bhh1,
                     const float* __restrict__ Wih2, const float* __restrict__ Whh2,
                     const float* __restrict__ bih2, const float* __restrict__ bhh2,
                     const float* __restrict__ Wlin, const float* __restrict__ blin,
                     float* __restrict__ out)
{
    extern __shared__ float sm[];
    float* W1s  = sm + OFF_W1;
    float* W2as = sm + OFF_W2A;
    float* W2bs = sm + OFF_W2B;
    float* H1D  = sm + OFF_H1D;
    float* H2D  = sm + OFF_H2D;
    float* B1s  = sm + OFF_B1;
    float* WI1s = sm + OFF_WI1;
    float* B2s  = sm + OFF_B2;
    float* WLs  = sm + OFF_WL;
    float* YP   = sm + OFF_YP;
    float* XS   = sm + OFF_XS;

    const int tid = threadIdx.x;

    // ---- stage weights gate-interleaved, k-major: W[k][u*4+g] = Wxx[g*51+u][k]
    for (int idx = tid; idx < H_ * CP; idx += NTH) {
        int kk = idx / CP, c = idx - kk * CP;
        int u = c >> 2, g = c & 3;
        float w1 = 0.f, wa = 0.f, wb = 0.f;
        if (u < H_) {
            int j = g * H_ + u;
            w1 = Whh1[j * H_ + kk];
            wa = Wih2[j * H_ + kk];
            wb = Whh2[j * H_ + kk];
        }
        W1s[idx] = w1; W2as[idx] = wa; W2bs[idx] = wb;
    }
    for (int c = tid; c < CP; c += NTH) {
        int u = c >> 2, g = c & 3;
        bool v = (u < H_);
        int j = g * H_ + u;
        B1s[c]  = v ? (bih1[j] + bhh1[j]) : 0.f;
        WI1s[c] = v ? Wih1[j] : 0.f;
        B2s[c]  = v ? (bih2[j] + bhh2[j]) : 0.f;
    }
    if (tid < 64) WLs[tid] = (tid < H_) ? Wlin[tid] : ((tid == 56) ? blin[0] : 0.f);
    for (int idx = tid; idx < 2 * H1BUF; idx += NTH) H1D[idx] = 0.f;
    for (int idx = tid; idx < H1BUF; idx += NTH)     H2D[idx] = 0.f;
    for (int idx = tid; idx < 1024; idx += NTH)      YP[idx]  = 0.f;
    __syncthreads();

    // roles: warps 0-3 (grp0) = layer1 + y/x service; warps 4-7 (grp1) = layer2
    const int grp = tid >> 7;
    const int lt  = tid & 127;
    const int mg  = lt & 15;       // 16 m-groups of 4 rows
    const int cg  = lt >> 4;       // 8 c-groups of 28 cols (7 u's)
    const int mb  = mg * 4;
    const int cb  = cg * 28;
    const int ub  = cg * 7;
    const int m0  = blockIdx.x * 64;

    u64 acc[56];                   // 4 m x 14 u64 (28 gate cols)
    float cr[28];                  // c-state: 4 m x 7 u
#pragma unroll
    for (int q = 0; q < 28; ++q) cr[q] = 0.f;

    // ---- prologue (grp0): gates1(0) = b1 + x(0)*Wih1  (h1(-1)=0) ----
    if (!grp) {
        const ulonglong2* Bp = (const ulonglong2*)(B1s + cb);
        const ulonglong2* Wp = (const ulonglong2*)(WI1s + cb);
        u64 wx[14];
#pragma unroll
        for (int j = 0; j < 7; ++j) { ulonglong2 w = Wp[j]; wx[2*j] = w.x; wx[2*j+1] = w.y; }
#pragma unroll
        for (int mm = 0; mm < 4; ++mm) {
            float xv = x[(size_t)(m0 + mb + mm) * T_];
            u64 xd = pack2(xv, xv);
#pragma unroll
            for (int j = 0; j < 7; ++j) {
                ulonglong2 b = Bp[j];
                acc[mm*14 + 2*j]     = fma2(xd, wx[2*j],     b.x);
                acc[mm*14 + 2*j + 1] = fma2(xd, wx[2*j + 1], b.y);
            }
        }
    }

    for (int i = 0; i <= T_; ++i) {
        // ================= Segment A =================
        if (!grp) {
            if (lt < 64) {
                // stage x for step i+1
                int tn = (i + 1 < T_) ? (i + 1) : (T_ - 1);
                XS[((i + 1) & 1) * 64 + lt] = x[(size_t)(m0 + lt) * T_ + tn];
                // y writer: step i-2
                if (i >= 2) {
                    const float* yp = YP + (i & 1) * 512;
                    float y = WLs[56];
#pragma unroll
                    for (int j = 0; j < 8; ++j) y += yp[j * 64 + lt];
                    out[(size_t)(m0 + lt) * T_ + (i - 2)] = y;
                }
            }
            // activation layer1, step i -> h1(i) (dup, buffer i&1)
            if (i < T_) {
                float* Hw = H1D + (i & 1) * H1BUF;
#pragma unroll
                for (int mm = 0; mm < 4; ++mm) {
#pragma unroll
                    for (int q = 0; q < 7; ++q) {
                        float iv, fv, gv, ov;
                        unpack2(acc[mm*14 + 2*q],     iv, fv);
                        unpack2(acc[mm*14 + 2*q + 1], gv, ov);
                        float c = sigm(fv) * cr[mm*7 + q] + sigm(iv) * tanh_(gv);
                        cr[mm*7 + q] = c;
                        float hh = sigm(ov) * tanh_(c);
                        *(float2*)(Hw + (ub + q) * RS + (mb + mm) * 2) = make_float2(hh, hh);
                    }
                }
            }
        } else {
            // GEMM layer2, step i-1: Wih2*h1(i-1) + Whh2*h2(i-2) + b2
            if (i >= 1) {
                const ulonglong2* Bp = (const ulonglong2*)(B2s + cb);
#pragma unroll
                for (int mm = 0; mm < 4; ++mm) {
#pragma unroll
                    for (int j = 0; j < 7; ++j) {
                        ulonglong2 b = Bp[j];
                        acc[mm*14 + 2*j] = b.x; acc[mm*14 + 2*j + 1] = b.y;
                    }
                }
                const float* H1r = H1D + ((i - 1) & 1) * H1BUF;
#pragma unroll 1
                for (int kk = 0; kk < H_; ++kk) {
                    const float* hp1 = H1r + kk * RS + mb * 2;
                    const float* hp2 = H2D + kk * RS + mb * 2;
                    ulonglong2 hA = *(const ulonglong2*)(hp1);
                    ulonglong2 hB = *(const ulonglong2*)(hp1 + 4);
                    ulonglong2 gA = *(const ulonglong2*)(hp2);
                    ulonglong2 gB = *(const ulonglong2*)(hp2 + 4);
                    u64 h1v[4] = {hA.x, hA.y, hB.x, hB.y};
                    u64 h2v[4] = {gA.x, gA.y, gB.x, gB.y};
                    const ulonglong2* wpa = (const ulonglong2*)(W2as + kk * CP + cb);
                    const ulonglong2* wpb = (const ulonglong2*)(W2bs + kk * CP + cb);
                    u64 wa[14], wb[14];
#pragma unroll
                    for (int j = 0; j < 7; ++j) {
                        ulonglong2 a = wpa[j]; wa[2*j] = a.x; wa[2*j+1] = a.y;
                        ulonglong2 b = wpb[j]; wb[2*j] = b.x; wb[2*j+1] = b.y;
                    }
#pragma unroll
                    for (int mm = 0; mm < 4; ++mm) {
#pragma unroll
                        for (int j = 0; j < 14; ++j)
                            acc[mm*14 + j] = fma2(h1v[mm], wa[j], acc[mm*14 + j]);
#pragma unroll
                        for (int j = 0; j < 14; ++j)
                            acc[mm*14 + j] = fma2(h2v[mm], wb[j], acc[mm*14 + j]);
                    }
                }
            }
        }
        __syncthreads();

        // ================= Segment B =================
        if (!grp) {
            // GEMM layer1, step i+1: Whh1*h1(i) + x(i+1)*Wih1 + b1
            if (i + 1 < T_) {
                const ulonglong2* Bp = (const ulonglong2*)(B1s + cb);
#pragma unroll
                for (int mm = 0; mm < 4; ++mm) {
#pragma unroll
                    for (int j = 0; j < 7; ++j) {
                        ulonglong2 b = Bp[j];
                        acc[mm*14 + 2*j] = b.x; acc[mm*14 + 2*j + 1] = b.y;
                    }
                }
                const float* Hr = H1D + (i & 1) * H1BUF;
#pragma unroll 2
                for (int kk = 0; kk < H_; ++kk) {
                    const float* hp = Hr + kk * RS + mb * 2;
                    ulonglong2 hA = *(const ulonglong2*)(hp);
                    ulonglong2 hB = *(const ulonglong2*)(hp + 4);
                    u64 h1v[4] = {hA.x, hA.y, hB.x, hB.y};
                    const ulonglong2* wp = (const ulonglong2*)(W1s + kk * CP + cb);
                    u64 wx[14];
#pragma unroll
                    for (int j = 0; j < 7; ++j) { ulonglong2 w = wp[j]; wx[2*j] = w.x; wx[2*j+1] = w.y; }
#pragma unroll
                    for (int mm = 0; mm < 4; ++mm) {
#pragma unroll
                        for (int j = 0; j < 14; ++j)
                            acc[mm*14 + j] = fma2(h1v[mm], wx[j], acc[mm*14 + j]);
                    }
                }
                // x-term from smem stage
                float4 xq = *(const float4*)(XS + ((i + 1) & 1) * 64 + mb);
                float xv[4] = {xq.x, xq.y, xq.z, xq.w};
                const ulonglong2* wp = (const ulonglong2*)(WI1s + cb);
                u64 wx[14];
#pragma unroll
                for (int j = 0; j < 7; ++j) { ulonglong2 w = wp[j]; wx[2*j] = w.x; wx[2*j+1] = w.y; }
#pragma unroll
                for (int mm = 0; mm < 4; ++mm) {
                    u64 xd = pack2(xv[mm], xv[mm]);
#pragma unroll
                    for (int j = 0; j < 14; ++j)
                        acc[mm*14 + j] = fma2(xd, wx[j], acc[mm*14 + j]);
                }
            }
        } else {
            // activation layer2, step i-1 -> h2(i-1) (dup), y partials
            if (i >= 1) {
                float py[4] = {0.f, 0.f, 0.f, 0.f};
#pragma unroll
                for (int q = 0; q < 7; ++q) {
                    float wl = WLs[ub + q];
#pragma unroll
                    for (int mm = 0; mm < 4; ++mm) {
                        float iv, fv, gv, ov;
                        unpack2(acc[mm*14 + 2*q],     iv, fv);
                        unpack2(acc[mm*14 + 2*q + 1], gv, ov);
                        float c = sigm(fv) * cr[mm*7 + q] + sigm(iv) * tanh_(gv);
                        cr[mm*7 + q] = c;
                        float hh = sigm(ov) * tanh_(c);
                        *(float2*)(H2D + (ub + q) * RS + (mb + mm) * 2) = make_float2(hh, hh);
                        py[mm] = fmaf(wl, hh, py[mm]);
                    }
                }
                *(float4*)(YP + ((i - 1) & 1) * 512 + cg * 64 + mb) =
                    make_float4(py[0], py[1], py[2], py[3]);
            }
        }
        __syncthreads();
    }

    // final y for step T-1
    if (tid < 64) {
        const float* yp = YP + ((T_ - 1) & 1) * 512;
        float y = WLs[56];
#pragma unroll
        for (int j = 0; j < 8; ++j) y += yp[j * 64 + tid];
        out[(size_t)(m0 + tid) * T_ + (T_ - 1)] = y;
    }
}

extern "C" void kernel_launch(void* const* d_in, const int* in_sizes, int n_in,
                              void* d_out, int out_size) {
    const float* x    = (const float*)d_in[0];
    const float* Wih1 = (const float*)d_in[1];
    const float* Whh1 = (const float*)d_in[2];
    const float* bih1 = (const float*)d_in[3];
    const float* bhh1 = (const float*)d_in[4];
    const float* Wih2 = (const float*)d_in[5];
    const float* Whh2 = (const float*)d_in[6];
    const float* bih2 = (const float*)d_in[7];
    const float* bhh2 = (const float*)d_in[8];
    const float* Wlin = (const float*)d_in[9];
    const float* blin = (const float*)d_in[10];
    float* out = (float*)d_out;

    size_t smem = SMEM_FLOATS * sizeof(float);   // ~225 KB
    cudaFuncSetAttribute(lstm_rnn_kernel,
                         cudaFuncAttributeMaxDynamicSharedMemorySize, (int)smem);
    lstm_rnn_kernel<<<B_ / 64, NTH, smem>>>(x, Wih1, Whh1, bih1, bhh1,
                                            Wih2, Whh2, bih2, bhh2,
                                            Wlin, blin, out);
}

// round 15
// speedup vs baseline: 1.7066x; 1.0281x over previous
#include <cuda_runtime.h>

// B=8192, T=2048, H=51
#define B_   8192
#define T_   2048
#define H_   51
#define CP   224            // 56*4 gate-interleaved cols (u=51..55 zero pad)
#define NTH  256
#define RS   128            // H row stride (floats), duplicated (h,h) layout
#define H1BUF (56*RS)       // 7168

typedef unsigned long long u64;

__device__ __forceinline__ u64 pack2(float lo, float hi) {
    u64 d; asm("mov.b64 %0, {%1, %2};" : "=l"(d) : "f"(lo), "f"(hi)); return d;
}
__device__ __forceinline__ void unpack2(u64 v, float& lo, float& hi) {
    asm("mov.b64 {%0, %1}, %2;" : "=f"(lo), "=f"(hi) : "l"(v));
}
__device__ __forceinline__ u64 fma2(u64 a, u64 b, u64 c) {
    u64 d; asm("fma.rn.f32x2 %0, %1, %2, %3;" : "=l"(d) : "l"(a), "l"(b), "l"(c)); return d;
}
__device__ __forceinline__ float ex2f(float x) { float r; asm("ex2.approx.f32 %0, %1;" : "=f"(r) : "f"(x)); return r; }
__device__ __forceinline__ float rcpf(float x) { float r; asm("rcp.approx.f32 %0, %1;" : "=f"(r) : "f"(x)); return r; }
__device__ __forceinline__ float sigm(float x) {
    return rcpf(1.0f + ex2f(-1.4426950408889634f * x));
}
__device__ __forceinline__ float tanh_(float x) {
    float e = ex2f(2.8853900817779268f * x);
    return 1.0f - 2.0f * rcpf(e + 1.0f);
}

// Smem layout (float offsets)
#define OFF_W1   0           // [51][224]
#define OFF_W2A  11424
#define OFF_W2B  22848
#define OFF_H1D  34272       // [2][56][128] duplicated (h,h)
#define OFF_H2D  48608       // [56][128]    duplicated (h,h), single buffer
#define OFF_B1   55776       // 224
#define OFF_WI1  56000
#define OFF_B2   56224
#define OFF_WL   56448       // 64  (WL[56]=b_lin)
#define OFF_YP   56512       // [2][8][64]
#define OFF_XS   57536       // [2][64]
#define SMEM_FLOATS 57664    // 230,656 B

__global__ __launch_bounds__(NTH, 1)
void lstm_rnn_kernel(const float* __restrict__ x,
                     const float* __restrict__ Wih1, const float* __restrict__ Whh1,
                     const float* __restrict__ bih1, const float* __restrict__ bhh1,
                     const float* __restrict__ Wih2, const float* __restrict__ Whh2,
                     const float* __restrict__ bih2, const float* __restrict__ bhh2,
                     const float* __restrict__ Wlin, const float* __restrict__ blin,
                     float* __restrict__ out)
{
    extern __shared__ float sm[];
    float* W1s  = sm + OFF_W1;
    float* W2as = sm + OFF_W2A;
    float* W2bs = sm + OFF_W2B;
    float* H1D  = sm + OFF_H1D;
    float* H2D  = sm + OFF_H2D;
    float* B1s  = sm + OFF_B1;
    float* WI1s = sm + OFF_WI1;
    float* B2s  = sm + OFF_B2;
    float* WLs  = sm + OFF_WL;
    float* YP   = sm + OFF_YP;
    float* XS   = sm + OFF_XS;

    const int tid = threadIdx.x;

    // ---- stage weights gate-interleaved, k-major: W[k][u*4+g] = Wxx[g*51+u][k]
    for (int idx = tid; idx < H_ * CP; idx += NTH) {
        int kk = idx / CP, c = idx - kk * CP;
        int u = c >> 2, g = c & 3;
        float w1 = 0.f, wa = 0.f, wb = 0.f;
        if (u < H_) {
            int j = g * H_ + u;
            w1 = Whh1[j * H_ + kk];
            wa = Wih2[j * H_ + kk];
            wb = Whh2[j * H_ + kk];
        }
        W1s[idx] = w1; W2as[idx] = wa; W2bs[idx] = wb;
    }
    for (int c = tid; c < CP; c += NTH) {
        int u = c >> 2, g = c & 3;
        bool v = (u < H_);
        int j = g * H_ + u;
        B1s[c]  = v ? (bih1[j] + bhh1[j]) : 0.f;
        WI1s[c] = v ? Wih1[j] : 0.f;
        B2s[c]  = v ? (bih2[j] + bhh2[j]) : 0.f;
    }
    if (tid < 64) WLs[tid] = (tid < H_) ? Wlin[tid] : ((tid == 56) ? blin[0] : 0.f);
    for (int idx = tid; idx < 2 * H1BUF; idx += NTH) H1D[idx] = 0.f;
    for (int idx = tid; idx < H1BUF; idx += NTH)     H2D[idx] = 0.f;
    for (int idx = tid; idx < 1024; idx += NTH)      YP[idx]  = 0.f;
    __syncthreads();

    // roles: warps 0-3 (grp0) = layer1 + y/x service; warps 4-7 (grp1) = layer2
    const int grp = tid >> 7;
    const int lt  = tid & 127;
    const int mg  = lt & 15;       // 16 m-groups of 4 rows
    const int cg  = lt >> 4;       // 8 c-groups of 28 cols (7 u's)
    const int mb  = mg * 4;
    const int cb  = cg * 28;
    const int ub  = cg * 7;
    const int m0  = blockIdx.x * 64;

    u64 acc[56];                   // 4 m x 14 u64 (28 gate cols)
    float cr[28];                  // c-state: 4 m x 7 u
#pragma unroll
    for (int q = 0; q < 28; ++q) cr[q] = 0.f;

    // ---- prologue (grp0): gates1(0) = b1 + x(0)*Wih1  (h1(-1)=0) ----
    if (!grp) {
        const ulonglong2* Bp = (const ulonglong2*)(B1s + cb);
        const ulonglong2* Wp = (const ulonglong2*)(WI1s + cb);
#pragma unroll
        for (int mm = 0; mm < 4; ++mm) {
            float xv = x[(size_t)(m0 + mb + mm) * T_];
            u64 xd = pack2(xv, xv);
#pragma unroll
            for (int j = 0; j < 7; ++j) {
                ulonglong2 b = Bp[j], w = Wp[j];
                acc[mm*14 + 2*j]     = fma2(xd, w.x, b.x);
                acc[mm*14 + 2*j + 1] = fma2(xd, w.y, b.y);
            }
        }
    }

    for (int i = 0; i <= T_; ++i) {
        // ================= Segment A =================
        if (!grp) {
            if (lt < 64) {
                // stage x for step i+1
                int tn = (i + 1 < T_) ? (i + 1) : (T_ - 1);
                XS[((i + 1) & 1) * 64 + lt] = x[(size_t)(m0 + lt) * T_ + tn];
                // y writer: step i-2
                if (i >= 2) {
                    const float* yp = YP + (i & 1) * 512;
                    float y = WLs[56];
#pragma unroll
                    for (int j = 0; j < 8; ++j) y += yp[j * 64 + lt];
                    out[(size_t)(m0 + lt) * T_ + (i - 2)] = y;
                }
            }
            // activation layer1, step i -> h1(i) (dup, buffer i&1)
            if (i < T_) {
                float* Hw = H1D + (i & 1) * H1BUF;
#pragma unroll
                for (int mm = 0; mm < 4; ++mm) {
#pragma unroll
                    for (int q = 0; q < 7; ++q) {
                        float iv, fv, gv, ov;
                        unpack2(acc[mm*14 + 2*q],     iv, fv);
                        unpack2(acc[mm*14 + 2*q + 1], gv, ov);
                        float c = sigm(fv) * cr[mm*7 + q] + sigm(iv) * tanh_(gv);
                        cr[mm*7 + q] = c;
                        float hh = sigm(ov) * tanh_(c);
                        *(float2*)(Hw + (ub + q) * RS + (mb + mm) * 2) = make_float2(hh, hh);
                    }
                }
            }
        } else {
            // GEMM layer2, step i-1: two passes (h1-pass then h2-pass)
            if (i >= 1) {
                const ulonglong2* Bp = (const ulonglong2*)(B2s + cb);
#pragma unroll
                for (int mm = 0; mm < 4; ++mm) {
#pragma unroll
                    for (int j = 0; j < 7; ++j) {
                        ulonglong2 b = Bp[j];
                        acc[mm*14 + 2*j] = b.x; acc[mm*14 + 2*j + 1] = b.y;
                    }
                }
                const float* H1r = H1D + ((i - 1) & 1) * H1BUF;
                // ---- pass A: + Wih2 * h1(i-1)
#pragma unroll 2
                for (int kk = 0; kk < H_; ++kk) {
                    const float* hp = H1r + kk * RS + mb * 2;
                    ulonglong2 hA = *(const ulonglong2*)(hp);
                    ulonglong2 hB = *(const ulonglong2*)(hp + 4);
                    u64 hv[4] = {hA.x, hA.y, hB.x, hB.y};
                    const ulonglong2* wp = (const ulonglong2*)(W2as + kk * CP + cb);
#pragma unroll
                    for (int j = 0; j < 7; ++j) {
                        ulonglong2 w = wp[j];
#pragma unroll
                        for (int mm = 0; mm < 4; ++mm) {
                            acc[mm*14 + 2*j]     = fma2(hv[mm], w.x, acc[mm*14 + 2*j]);
                            acc[mm*14 + 2*j + 1] = fma2(hv[mm], w.y, acc[mm*14 + 2*j + 1]);
                        }
                    }
                }
                // ---- pass B: + Whh2 * h2(i-2)
#pragma unroll 2
                for (int kk = 0; kk < H_; ++kk) {
                    const float* hp = H2D + kk * RS + mb * 2;
                    ulonglong2 hA = *(const ulonglong2*)(hp);
                    ulonglong2 hB = *(const ulonglong2*)(hp + 4);
                    u64 hv[4] = {hA.x, hA.y, hB.x, hB.y};
                    const ulonglong2* wp = (const ulonglong2*)(W2bs + kk * CP + cb);
#pragma unroll
                    for (int j = 0; j < 7; ++j) {
                        ulonglong2 w = wp[j];
#pragma unroll
                        for (int mm = 0; mm < 4; ++mm) {
                            acc[mm*14 + 2*j]     = fma2(hv[mm], w.x, acc[mm*14 + 2*j]);
                            acc[mm*14 + 2*j + 1] = fma2(hv[mm], w.y, acc[mm*14 + 2*j + 1]);
                        }
                    }
                }
            }
        }
        __syncthreads();

        // ================= Segment B =================
        if (!grp) {
            // GEMM layer1, step i+1: Whh1*h1(i) + x(i+1)*Wih1 + b1
            if (i + 1 < T_) {
                const ulonglong2* Bp = (const ulonglong2*)(B1s + cb);
#pragma unroll
                for (int mm = 0; mm < 4; ++mm) {
#pragma unroll
                    for (int j = 0; j < 7; ++j) {
                        ulonglong2 b = Bp[j];
                        acc[mm*14 + 2*j] = b.x; acc[mm*14 + 2*j + 1] = b.y;
                    }
                }
                const float* Hr = H1D + (i & 1) * H1BUF;
#pragma unroll 2
                for (int kk = 0; kk < H_; ++kk) {
                    const float* hp = Hr + kk * RS + mb * 2;
                    ulonglong2 hA = *(const ulonglong2*)(hp);
                    ulonglong2 hB = *(const ulonglong2*)(hp + 4);
                    u64 hv[4] = {hA.x, hA.y, hB.x, hB.y};
                    const ulonglong2* wp = (const ulonglong2*)(W1s + kk * CP + cb);
#pragma unroll
                    for (int j = 0; j < 7; ++j) {
                        ulonglong2 w = wp[j];
#pragma unroll
                        for (int mm = 0; mm < 4; ++mm) {
                            acc[mm*14 + 2*j]     = fma2(hv[mm], w.x, acc[mm*14 + 2*j]);
                            acc[mm*14 + 2*j + 1] = fma2(hv[mm], w.y, acc[mm*14 + 2*j + 1]);
                        }
                    }
                }
                // x-term from smem stage
                float4 xq = *(const float4*)(XS + ((i + 1) & 1) * 64 + mb);
                float xv[4] = {xq.x, xq.y, xq.z, xq.w};
                const ulonglong2* wp = (const ulonglong2*)(WI1s + cb);
#pragma unroll
                for (int j = 0; j < 7; ++j) {
                    ulonglong2 w = wp[j];
#pragma unroll
                    for (int mm = 0; mm < 4; ++mm) {
                        u64 xd = pack2(xv[mm], xv[mm]);
                        acc[mm*14 + 2*j]     = fma2(xd, w.x, acc[mm*14 + 2*j]);
                        acc[mm*14 + 2*j + 1] = fma2(xd, w.y, acc[mm*14 + 2*j + 1]);
                    }
                }
            }
        } else {
            // activation layer2, step i-1 -> h2(i-1) (dup), y partials
            if (i >= 1) {
                float py[4] = {0.f, 0.f, 0.f, 0.f};
#pragma unroll
                for (int q = 0; q < 7; ++q) {
                    float wl = WLs[ub + q];
#pragma unroll
                    for (int mm = 0; mm < 4; ++mm) {
                        float iv, fv, gv, ov;
                        unpack2(acc[mm*14 + 2*q],     iv, fv);
                        unpack2(acc[mm*14 + 2*q + 1], gv, ov);
                        float c = sigm(fv) * cr[mm*7 + q] + sigm(iv) * tanh_(gv);
                        cr[mm*7 + q] = c;
                        float hh = sigm(ov) * tanh_(c);
                        *(float2*)(H2D + (ub + q) * RS + (mb + mm) * 2) = make_float2(hh, hh);
                        py[mm] = fmaf(wl, hh, py[mm]);
                    }
                }
                *(float4*)(YP + ((i - 1) & 1) * 512 + cg * 64 + mb) =
                    make_float4(py[0], py[1], py[2], py[3]);
            }
        }
        __syncthreads();
    }

    // final y for step T-1
    if (tid < 64) {
        const float* yp = YP + ((T_ - 1) & 1) * 512;
        float y = WLs[56];
#pragma unroll
        for (int j = 0; j < 8; ++j) y += yp[j * 64 + tid];
        out[(size_t)(m0 + tid) * T_ + (T_ - 1)] = y;
    }
}

extern "C" void kernel_launch(void* const* d_in, const int* in_sizes, int n_in,
                              void* d_out, int out_size) {
    const float* x    = (const float*)d_in[0];
    const float* Wih1 = (const float*)d_in[1];
    const float* Whh1 = (const float*)d_in[2];
    const float* bih1 = (const float*)d_in[3];
    const float* bhh1 = (const float*)d_in[4];
    const float* Wih2 = (const float*)d_in[5];
    const float* Whh2 = (const float*)d_in[6];
    const float* bih2 = (const float*)d_in[7];
    const float* bhh2 = (const float*)d_in[8];
    const float* Wlin = (const float*)d_in[9];
    const float* blin = (const float*)d_in[10];
    float* out = (float*)d_out;

    size_t smem = SMEM_FLOATS * sizeof(float);   // ~225 KB
    cudaFuncSetAttribute(lstm_rnn_kernel,
                         cudaFuncAttributeMaxDynamicSharedMemorySize, (int)smem);
    lstm_rnn_kernel<<<B_ / 64, NTH, smem>>>(x, Wih1, Whh1, bih1, bhh1,
                                            Wih2, Whh2, bih2, bhh2,
                                            Wlin, blin, out);
}